// round 13
// baseline (speedup 1.0000x reference)
#include <cuda_runtime.h>
#include <cuda_fp16.h>
#include <math.h>

#define Bsz 4096
#define Nn 512
#define Mm 64
#define SEQW 8
#define HID 256
#define COUT 128
#define IN_SIZE 73        // SEQW+1+Mm
#define PARAM 70          // M + 1 + 1 + 3 + 1
#define REPR 268          // 2*PARAM + 2*M
#define ROWS 8
#define SROW 64           // smem row stride in halves (128 B rows)
#define NPERS 456         // persistent CTAs = 152 SMs x 3

// ---------------- scratch (no cudaMalloc allowed) ----------------
__device__ float g_ctrl[Bsz * COUT];     // controller output
__device__ float g_kt[Bsz * 2 * Mm];     // tanh'd keys [b][head][m]
__device__ float g_scal[Bsz * 16];       // per (b,head): knorm,beta,gg,sm0..2,gamma
__device__ float g_ae[Bsz * Mm];         // a - e

__device__ __forceinline__ float lrelu(float x)    { return x > 0.f ? x : 0.01f * x; }
__device__ __forceinline__ float sigmoidf_(float x){ return 1.f / (1.f + __expf(-x)); }
__device__ __forceinline__ float softplusf_(float x){ return x > 20.f ? x : log1pf(expf(x)); }

// ========= Kernel 1: controller + repr (8 rows, 512 thr, split-K) ===========
__global__ void __launch_bounds__(512)
ctrl_kernel(const float* __restrict__ x, const float* __restrict__ prev_read,
            const float* __restrict__ W0, const float* __restrict__ b0,
            const float* __restrict__ W1, const float* __restrict__ b1,
            const float* __restrict__ Wout, const float* __restrict__ bout,
            const float* __restrict__ rW, const float* __restrict__ rb)
{
    __shared__ float cin[IN_SIZE * ROWS];   // [i][r]
    __shared__ float h0s[HID * ROWS];       // [i][r]
    __shared__ float h1s[HID * ROWS];       // [i][r]
    __shared__ float cos_[COUT * ROWS];     // [i][r]
    __shared__ float rep[ROWS][REPR];
    __shared__ float psum[4096];            // split-K partials

    const int tid = threadIdx.x;
    const int bbase = blockIdx.x * ROWS;

    for (int idx = tid; idx < IN_SIZE * ROWS; idx += 512) {
        int i = idx >> 3, r = idx & 7;
        int b = bbase + r;
        cin[idx] = (i < SEQW + 1) ? x[b * (SEQW + 1) + i]
                                  : prev_read[b * Mm + (i - (SEQW + 1))];
    }
    __syncthreads();

    // ---- layer 0: 73 -> 256, i split in 2 halves ----
    {
        int j = tid & 255, h = tid >> 8;
        int i0 = h ? 37 : 0, i1 = h ? 73 : 37;
        float a0=0,a1=0,a2=0,a3=0,a4=0,a5=0,a6=0,a7=0;
        #pragma unroll 4
        for (int i = i0; i < i1; i++) {
            float w = W0[i * HID + j];
            float4 hA = *(const float4*)&cin[i * 8];
            float4 hB = *(const float4*)&cin[i * 8 + 4];
            a0 += hA.x*w; a1 += hA.y*w; a2 += hA.z*w; a3 += hA.w*w;
            a4 += hB.x*w; a5 += hB.y*w; a6 += hB.z*w; a7 += hB.w*w;
        }
        *(float4*)&psum[(h*256+j)*8]   = make_float4(a0,a1,a2,a3);
        *(float4*)&psum[(h*256+j)*8+4] = make_float4(a4,a5,a6,a7);
    }
    __syncthreads();
    {
        int j = tid >> 1, q = (tid & 1) * 4;
        float4 pA = *(const float4*)&psum[j*8 + q];
        float4 pB = *(const float4*)&psum[(256+j)*8 + q];
        float bb = b0[j];
        *(float4*)&h0s[j*8+q] = make_float4(
            lrelu(pA.x+pB.x+bb), lrelu(pA.y+pB.y+bb),
            lrelu(pA.z+pB.z+bb), lrelu(pA.w+pB.w+bb));
    }
    __syncthreads();

    // ---- layer 1: 256 -> 256, i split in 2 halves ----
    {
        int j = tid & 255, h = tid >> 8;
        int i0 = h * 128, i1 = i0 + 128;
        float a0=0,a1=0,a2=0,a3=0,a4=0,a5=0,a6=0,a7=0;
        #pragma unroll 8
        for (int i = i0; i < i1; i++) {
            float w = W1[i * HID + j];
            float4 hA = *(const float4*)&h0s[i * 8];
            float4 hB = *(const float4*)&h0s[i * 8 + 4];
            a0 += hA.x*w; a1 += hA.y*w; a2 += hA.z*w; a3 += hA.w*w;
            a4 += hB.x*w; a5 += hB.y*w; a6 += hB.z*w; a7 += hB.w*w;
        }
        *(float4*)&psum[(h*256+j)*8]   = make_float4(a0,a1,a2,a3);
        *(float4*)&psum[(h*256+j)*8+4] = make_float4(a4,a5,a6,a7);
    }
    __syncthreads();
    {
        int j = tid >> 1, q = (tid & 1) * 4;
        float4 pA = *(const float4*)&psum[j*8 + q];
        float4 pB = *(const float4*)&psum[(256+j)*8 + q];
        float bb = b1[j];
        *(float4*)&h1s[j*8+q] = make_float4(
            lrelu(pA.x+pB.x+bb), lrelu(pA.y+pB.y+bb),
            lrelu(pA.z+pB.z+bb), lrelu(pA.w+pB.w+bb));
    }
    __syncthreads();

    // ---- ctrl out: 256 -> 128, tanh, i split in 4 quarters ----
    {
        int j = tid & 127, qt = tid >> 7;
        int i0 = qt * 64, i1 = i0 + 64;
        float a0=0,a1=0,a2=0,a3=0,a4=0,a5=0,a6=0,a7=0;
        #pragma unroll 8
        for (int i = i0; i < i1; i++) {
            float w = Wout[i * COUT + j];
            float4 hA = *(const float4*)&h1s[i * 8];
            float4 hB = *(const float4*)&h1s[i * 8 + 4];
            a0 += hA.x*w; a1 += hA.y*w; a2 += hA.z*w; a3 += hA.w*w;
            a4 += hB.x*w; a5 += hB.y*w; a6 += hB.z*w; a7 += hB.w*w;
        }
        *(float4*)&psum[(qt*128+j)*8]   = make_float4(a0,a1,a2,a3);
        *(float4*)&psum[(qt*128+j)*8+4] = make_float4(a4,a5,a6,a7);
    }
    __syncthreads();
    if (tid < 256) {
        int j = tid >> 1, q = (tid & 1) * 4;
        float4 p0 = *(const float4*)&psum[(0*128+j)*8 + q];
        float4 p1 = *(const float4*)&psum[(1*128+j)*8 + q];
        float4 p2 = *(const float4*)&psum[(2*128+j)*8 + q];
        float4 p3 = *(const float4*)&psum[(3*128+j)*8 + q];
        float bb = bout[j];
        float v0 = tanhf(p0.x+p1.x+p2.x+p3.x+bb);
        float v1 = tanhf(p0.y+p1.y+p2.y+p3.y+bb);
        float v2 = tanhf(p0.z+p1.z+p2.z+p3.z+bb);
        float v3 = tanhf(p0.w+p1.w+p2.w+p3.w+bb);
        *(float4*)&cos_[j*8+q] = make_float4(v0,v1,v2,v3);
        int r0 = q;
        g_ctrl[(bbase + r0 + 0) * COUT + j] = v0;
        g_ctrl[(bbase + r0 + 1) * COUT + j] = v1;
        g_ctrl[(bbase + r0 + 2) * COUT + j] = v2;
        g_ctrl[(bbase + r0 + 3) * COUT + j] = v3;
    }
    __syncthreads();

    // ---- repr: 128 -> 268 ----
    for (int o = tid; o < REPR; o += 512) {
        float bb = rb[o];
        float a0=bb,a1=bb,a2=bb,a3=bb,a4=bb,a5=bb,a6=bb,a7=bb;
        #pragma unroll 8
        for (int i = 0; i < COUT; i++) {
            float w = rW[i * REPR + o];
            float4 hA = *(const float4*)&cos_[i * 8];
            float4 hB = *(const float4*)&cos_[i * 8 + 4];
            a0 += hA.x*w; a1 += hA.y*w; a2 += hA.z*w; a3 += hA.w*w;
            a4 += hB.x*w; a5 += hB.y*w; a6 += hB.z*w; a7 += hB.w*w;
        }
        rep[0][o]=a0; rep[1][o]=a1; rep[2][o]=a2; rep[3][o]=a3;
        rep[4][o]=a4; rep[5][o]=a5; rep[6][o]=a6; rep[7][o]=a7;
    }
    __syncthreads();

    for (int idx = tid; idx < ROWS * REPR; idx += 512) {
        int r = idx / REPR, o = idx % REPR;
        float v = rep[r][o], t;
        if (o < 2 * PARAM) {
            int oh = o % PARAM;
            if (oh < Mm)        t = tanhf(v);
            else if (oh == Mm)  t = softplusf_(v);
            else if (oh == Mm+1)t = sigmoidf_(v);
            else if (oh < Mm+5) t = v;
            else                t = softplusf_(v)+1.f;
        } else if (o < 2 * PARAM + Mm) t = sigmoidf_(v);
        else                            t = tanhf(v);
        rep[r][o] = t;
    }
    __syncthreads();

    const int lane = tid & 31, wid = tid >> 5;
    if (wid < ROWS) {
        int r = wid, b = bbase + r;
        #pragma unroll
        for (int h = 0; h < 2; h++) {
            float v0 = rep[r][h * PARAM + lane];
            float v1 = rep[r][h * PARAM + lane + 32];
            g_kt[b * 128 + h * 64 + lane]      = v0;
            g_kt[b * 128 + h * 64 + lane + 32] = v1;
            float ss = v0 * v0 + v1 * v1;
            #pragma unroll
            for (int o = 16; o; o >>= 1) ss += __shfl_xor_sync(0xffffffffu, ss, o);
            if (lane == 0) g_scal[b * 16 + h * 8 + 0] = sqrtf(ss);
        }
    }
    if (tid < 16) {
        int r = tid >> 1, h = tid & 1, b = bbase + r;
        const float* rp = &rep[r][h * PARAM];
        float* sp = &g_scal[b * 16 + h * 8];
        sp[1] = rp[Mm];
        sp[2] = rp[Mm + 1];
        sp[6] = rp[Mm + 5];
        float s0 = rp[Mm + 2], s1 = rp[Mm + 3], s2 = rp[Mm + 4];
        float mx = fmaxf(s0, fmaxf(s1, s2));
        float e0 = __expf(s0 - mx), e1 = __expf(s1 - mx), e2 = __expf(s2 - mx);
        float inv = 1.f / (e0 + e1 + e2);
        sp[3] = e0 * inv; sp[4] = e1 * inv; sp[5] = e2 * inv;
    }
    {
        int r = tid >> 6, m = tid & 63;
        g_ae[(bbase + r) * Mm + m] =
            rep[r][2 * PARAM + Mm + m] - rep[r][2 * PARAM + m];
    }
}

// ================= block reduction helper (512 threads) =====================
__device__ __forceinline__ void block_red2(float a, float b, float* oa, float* ob,
                                           float* scratch, bool is_max)
{
    #pragma unroll
    for (int o = 16; o; o >>= 1) {
        float ta = __shfl_xor_sync(0xffffffffu, a, o);
        float tb = __shfl_xor_sync(0xffffffffu, b, o);
        if (is_max) { a = fmaxf(a, ta); b = fmaxf(b, tb); }
        else        { a += ta;          b += tb; }
    }
    int w = threadIdx.x >> 5;
    __syncthreads();
    if ((threadIdx.x & 31) == 0) { scratch[w] = a; scratch[16 + w] = b; }
    __syncthreads();
    if (threadIdx.x < 16) {
        float va = scratch[threadIdx.x];
        float vb = scratch[16 + threadIdx.x];
        #pragma unroll
        for (int o = 8; o; o >>= 1) {
            float ta = __shfl_xor_sync(0xffffu, va, o);
            float tb = __shfl_xor_sync(0xffffu, vb, o);
            if (is_max) { va = fmaxf(va, ta); vb = fmaxf(vb, tb); }
            else        { va += ta;           vb += tb; }
        }
        if (threadIdx.x == 0) { scratch[0] = va; scratch[16] = vb; }
    }
    __syncthreads();
    *oa = scratch[0]; *ob = scratch[16];
}

// ===== Kernel 2: persistent fp16-stash addressing + fused out projection ====
// R8 structure (inline scores during the single DRAM stream), persistent
// grid of 456 CTAs (152 SMs x 3) looping over ~9 elements each; the output
// projection runs in the tail (oW stays L1-hot across iterations).
__global__ void __launch_bounds__(512, 3)
addr_kernel(const float* __restrict__ bank, const float* __restrict__ w_read,
            const float* __restrict__ w_write,
            const float* __restrict__ oW, const float* __restrict__ obias,
            float* __restrict__ out)
{
    extern __shared__ __half sbank[];     // Nn * SROW halves = 65536 B
    __shared__ float skt[128];
    __shared__ float sr[Nn], sw_[Nn];     // scores -> final weights
    __shared__ float wg2[2 * Nn];         // gate weights, then read partials
    __shared__ float aed[Mm];
    __shared__ float bc[32];
    __shared__ float rdv[64];

    float* wgr = wg2;
    float* wgw = wg2 + Nn;
    float* red = wg2;                     // aliased: wgr/wgw dead by pass 2

    const int tid = threadIdx.x;
    const int lane = tid & 31, wid = tid >> 5;
    const int g8 = tid >> 3;              // row-group 0..63
    const int mo = (tid & 7) * 8;         // m offset (floats/halves)

    for (int b = blockIdx.x; b < Bsz; b += NPERS) {

        if (tid < 128) skt[tid] = g_kt[b * 128 + tid];
        if (tid < 64)  aed[tid] = g_ae[b * 64 + tid];
        __syncthreads();   // also serves as end-of-previous-element barrier

        const float4* gb4 = (const float4*)(bank + (size_t)b * Nn * Mm);
        const float* sp = &g_scal[b * 16];

        // ---- pass 1: stream bank once (pipelined) -> scores + fp16 stash ----
        {
            const float4 ktr0 = *(const float4*)&skt[mo];
            const float4 ktr1 = *(const float4*)&skt[mo + 4];
            const float4 ktw0 = *(const float4*)&skt[64 + mo];
            const float4 ktw1 = *(const float4*)&skt[64 + mo + 4];
            const float knorm_r = sp[0], beta_r = sp[1];
            const float knorm_w = sp[8], beta_w = sp[9];

            const float4* row0 = gb4 + g8 * 16 + (mo >> 2);
            float4 x0 = __ldcs(&row0[0]);
            float4 x1 = __ldcs(&row0[1]);
            #pragma unroll
            for (int it = 0; it < 8; it++) {
                float4 y0, y1;
                if (it < 7) {
                    const float4* rn = gb4 + ((it + 1) * 64 + g8) * 16 + (mo >> 2);
                    y0 = __ldcs(&rn[0]);
                    y1 = __ldcs(&rn[1]);
                }
                int n = it * 64 + g8;
                union { __half2 h[4]; uint4 u; } cv;
                cv.h[0] = __floats2half2_rn(x0.x, x0.y);
                cv.h[1] = __floats2half2_rn(x0.z, x0.w);
                cv.h[2] = __floats2half2_rn(x1.x, x1.y);
                cv.h[3] = __floats2half2_rn(x1.z, x1.w);
                *(uint4*)&sbank[n * SROW + mo] = cv.u;

                float dr = x0.x*ktr0.x + x0.y*ktr0.y + x0.z*ktr0.z + x0.w*ktr0.w
                         + x1.x*ktr1.x + x1.y*ktr1.y + x1.z*ktr1.z + x1.w*ktr1.w;
                float dw = x0.x*ktw0.x + x0.y*ktw0.y + x0.z*ktw0.z + x0.w*ktw0.w
                         + x1.x*ktw1.x + x1.y*ktw1.y + x1.z*ktw1.z + x1.w*ktw1.w;
                float ss = x0.x*x0.x + x0.y*x0.y + x0.z*x0.z + x0.w*x0.w
                         + x1.x*x1.x + x1.y*x1.y + x1.z*x1.z + x1.w*x1.w;
                #pragma unroll
                for (int o = 4; o; o >>= 1) {
                    dr += __shfl_xor_sync(0xffffffffu, dr, o);
                    dw += __shfl_xor_sync(0xffffffffu, dw, o);
                    ss += __shfl_xor_sync(0xffffffffu, ss, o);
                }
                if ((tid & 7) == 0) {
                    float nb = sqrtf(ss);
                    sr[n]  = beta_r * dr / fmaxf(nb * knorm_r, 1e-8f);
                    sw_[n] = beta_w * dw / fmaxf(nb * knorm_w, 1e-8f);
                }
                x0 = y0; x1 = y1;
            }
        }
        __syncthreads();

        // ---- softmax over N, gate interpolation ----
        {
            const float gg_r = sp[2], gg_w = sp[10];
            float vr = sr[tid], vw = sw_[tid];
            float mr, mw;  block_red2(vr, vw, &mr, &mw, bc, true);
            float er = __expf(vr - mr), ew = __expf(vw - mw);
            float srr, sww;  block_red2(er, ew, &srr, &sww, bc, false);
            float wgrv = gg_r * (er / srr) + (1.f - gg_r) * w_read [(size_t)b * Nn + tid];
            float wgwv = gg_w * (ew / sww) + (1.f - gg_w) * w_write[(size_t)b * Nn + tid];
            wgr[tid] = wgrv; wgw[tid] = wgwv;
        }
        __syncthreads();

        // ---- circular shift (-1,0,1) + sharpen + renormalize ----
        {
            const float sm0_r = sp[3], sm1_r = sp[4], sm2_r = sp[5], gam_r = sp[6];
            const float sm0_w = sp[11], sm1_w = sp[12], sm2_w = sp[13], gam_w = sp[14];
            int nm1 = (tid - 1) & (Nn - 1), np1 = (tid + 1) & (Nn - 1);
            float wsr = wgr[nm1] * sm0_r + wgr[tid] * sm1_r + wgr[np1] * sm2_r;
            float wsw = wgw[nm1] * sm0_w + wgw[tid] * sm1_w + wgw[np1] * sm2_w;
            float pr = powf(wsr, gam_r), pw = powf(wsw, gam_w);
            float spr, spw; block_red2(pr, pw, &spr, &spw, bc, false);
            sr[tid]  = pr / spr;   // final read weights
            sw_[tid] = pw / spw;   // final write weights
        }
        __syncthreads();

        // ---- pass 2: smem only -> read partials + new_bank write ----
        {
            const float4 ae0 = *(const float4*)&aed[mo];
            const float4 ae1 = *(const float4*)&aed[mo + 4];
            float racc[8] = {0,0,0,0,0,0,0,0};
            float4* ob4 = (float4*)(out + (size_t)Bsz * SEQW + (size_t)b * Nn * Mm);
            #pragma unroll 2
            for (int it = 0; it < 8; it++) {
                int n = it * 64 + g8;
                union { uint4 u; __half2 h[4]; } cv;
                cv.u = *(const uint4*)&sbank[n * SROW + mo];
                float2 f0 = __half22float2(cv.h[0]);
                float2 f1 = __half22float2(cv.h[1]);
                float2 f2 = __half22float2(cv.h[2]);
                float2 f3 = __half22float2(cv.h[3]);
                float wwv = sw_[n], wrv = sr[n];
                float4 o0 = make_float4(f0.x + wwv*ae0.x, f0.y + wwv*ae0.y,
                                        f1.x + wwv*ae0.z, f1.y + wwv*ae0.w);
                float4 o1 = make_float4(f2.x + wwv*ae1.x, f2.y + wwv*ae1.y,
                                        f3.x + wwv*ae1.z, f3.y + wwv*ae1.w);
                float4* op = ob4 + n * 16 + (mo >> 2);
                __stcs(&op[0], o0);
                __stcs(&op[1], o1);
                racc[0] += wrv*f0.x; racc[1] += wrv*f0.y;
                racc[2] += wrv*f1.x; racc[3] += wrv*f1.y;
                racc[4] += wrv*f2.x; racc[5] += wrv*f2.y;
                racc[6] += wrv*f3.x; racc[7] += wrv*f3.y;
            }
            // reduce over the 4 row-groups within each warp (lanes xor 8, 16)
            #pragma unroll
            for (int k = 0; k < 8; k++) {
                racc[k] += __shfl_xor_sync(0xffffffffu, racc[k], 8);
                racc[k] += __shfl_xor_sync(0xffffffffu, racc[k], 16);
            }
            __syncthreads();   // wgr/wgw dead; red aliases them
            if (lane < 8) {
                #pragma unroll
                for (int k = 0; k < 8; k++)
                    red[wid * 64 + lane * 8 + k] = racc[k];
            }
        }
        __syncthreads();
        if (tid < 64) {
            float s = 0.f;
            #pragma unroll
            for (int w = 0; w < 16; w++) s += red[w * 64 + tid];
            rdv[tid] = s;
        }
        __syncthreads();

        // ---- fused out projection: warp o computes seq_out[b][o] ----
        if (wid < SEQW) {
            int o = wid;
            float acc = 0.f;
            #pragma unroll
            for (int k = lane; k < COUT + Mm; k += 32) {
                float v = (k < COUT) ? g_ctrl[(size_t)b * COUT + k] : rdv[k - COUT];
                acc += v * oW[k * SEQW + o];
            }
            #pragma unroll
            for (int s = 16; s; s >>= 1) acc += __shfl_xor_sync(0xffffffffu, acc, s);
            if (lane == 0)
                out[b * SEQW + o] = 1.f / (1.f + __expf(-(acc + obias[o])));
        }
        // next iteration's first __syncthreads() closes this element
    }
}

// ================= launch ====================================================
extern "C" void kernel_launch(void* const* d_in, const int* in_sizes, int n_in,
                              void* d_out, int out_size)
{
    const float* x         = (const float*)d_in[0];
    const float* prev_read = (const float*)d_in[1];
    const float* bank      = (const float*)d_in[2];
    const float* w_read    = (const float*)d_in[3];
    const float* w_write   = (const float*)d_in[4];
    const float* W0        = (const float*)d_in[5];
    const float* b0        = (const float*)d_in[6];
    const float* W1        = (const float*)d_in[7];
    const float* b1        = (const float*)d_in[8];
    const float* Wout      = (const float*)d_in[9];
    const float* bout      = (const float*)d_in[10];
    const float* rW        = (const float*)d_in[11];
    const float* rb        = (const float*)d_in[12];
    const float* oW        = (const float*)d_in[13];
    const float* ob        = (const float*)d_in[14];
    float* out = (float*)d_out;

    const int HBANK = Nn * SROW * (int)sizeof(__half);   // 65536 B dynamic smem
    cudaFuncSetAttribute(addr_kernel, cudaFuncAttributeMaxDynamicSharedMemorySize, HBANK);

    ctrl_kernel<<<Bsz / ROWS, 512>>>(x, prev_read, W0, b0, W1, b1, Wout, bout, rW, rb);
    addr_kernel<<<NPERS, 512, HBANK>>>(bank, w_read, w_write, oW, ob, out);
}

// round 14
// speedup vs baseline: 1.1772x; 1.1772x over previous
#include <cuda_runtime.h>
#include <cuda_fp16.h>
#include <math.h>

#define Bsz 4096
#define Nn 512
#define Mm 64
#define SEQW 8
#define HID 256
#define COUT 128
#define IN_SIZE 73        // SEQW+1+Mm
#define PARAM 70          // M + 1 + 1 + 3 + 1
#define REPR 268          // 2*PARAM + 2*M
#define ROWS 8
#define SROW 64           // smem row stride in halves (128 B rows, no pad)

// ---------------- scratch (no cudaMalloc allowed) ----------------
__device__ float g_ctrl[Bsz * COUT];     // controller output
__device__ float g_kt[Bsz * 2 * Mm];     // tanh'd keys [b][head][m]
__device__ float g_scal[Bsz * 16];       // per (b,head): knorm,beta,gg,sm0..2,gamma
__device__ float g_ae[Bsz * Mm];         // a - e
__device__ float g_read[Bsz * Mm];       // read vector

__device__ __forceinline__ float lrelu(float x)    { return x > 0.f ? x : 0.01f * x; }
__device__ __forceinline__ float sigmoidf_(float x){ return 1.f / (1.f + __expf(-x)); }
__device__ __forceinline__ float softplusf_(float x){ return x > 20.f ? x : log1pf(__expf(x)); }
__device__ __forceinline__ float tanhf_(float x)   {
    // |x|>9: tanh saturates to ±1 in fp32
    float e = __expf(2.f * x);
    float t = 1.f - 2.f / (e + 1.f);
    return (x > 9.f) ? 1.f : (x < -9.f ? -1.f : t);
}

// ========= Kernel 1: controller + repr (8 rows, 512 thr, split-K) ===========
__global__ void __launch_bounds__(512)
ctrl_kernel(const float* __restrict__ x, const float* __restrict__ prev_read,
            const float* __restrict__ W0, const float* __restrict__ b0,
            const float* __restrict__ W1, const float* __restrict__ b1,
            const float* __restrict__ Wout, const float* __restrict__ bout,
            const float* __restrict__ rW, const float* __restrict__ rb)
{
    __shared__ float cin[IN_SIZE * ROWS];   // [i][r]
    __shared__ float h0s[HID * ROWS];       // [i][r]
    __shared__ float h1s[HID * ROWS];       // [i][r]
    __shared__ float cos_[COUT * ROWS];     // [i][r]
    __shared__ float rep[ROWS][REPR];
    __shared__ float psum[4096];            // split-K partials

    const int tid = threadIdx.x;
    const int bbase = blockIdx.x * ROWS;

    for (int idx = tid; idx < IN_SIZE * ROWS; idx += 512) {
        int i = idx >> 3, r = idx & 7;
        int b = bbase + r;
        cin[idx] = (i < SEQW + 1) ? x[b * (SEQW + 1) + i]
                                  : prev_read[b * Mm + (i - (SEQW + 1))];
    }
    __syncthreads();

    // ---- layer 0: 73 -> 256, i split in 2 halves ----
    {
        int j = tid & 255, h = tid >> 8;
        int i0 = h ? 37 : 0, i1 = h ? 73 : 37;
        float a0=0,a1=0,a2=0,a3=0,a4=0,a5=0,a6=0,a7=0;
        #pragma unroll 4
        for (int i = i0; i < i1; i++) {
            float w = W0[i * HID + j];
            float4 hA = *(const float4*)&cin[i * 8];
            float4 hB = *(const float4*)&cin[i * 8 + 4];
            a0 += hA.x*w; a1 += hA.y*w; a2 += hA.z*w; a3 += hA.w*w;
            a4 += hB.x*w; a5 += hB.y*w; a6 += hB.z*w; a7 += hB.w*w;
        }
        *(float4*)&psum[(h*256+j)*8]   = make_float4(a0,a1,a2,a3);
        *(float4*)&psum[(h*256+j)*8+4] = make_float4(a4,a5,a6,a7);
    }
    __syncthreads();
    {
        int j = tid >> 1, q = (tid & 1) * 4;
        float4 pA = *(const float4*)&psum[j*8 + q];
        float4 pB = *(const float4*)&psum[(256+j)*8 + q];
        float bb = b0[j];
        *(float4*)&h0s[j*8+q] = make_float4(
            lrelu(pA.x+pB.x+bb), lrelu(pA.y+pB.y+bb),
            lrelu(pA.z+pB.z+bb), lrelu(pA.w+pB.w+bb));
    }
    __syncthreads();

    // ---- layer 1: 256 -> 256, i split in 2 halves ----
    {
        int j = tid & 255, h = tid >> 8;
        int i0 = h * 128, i1 = i0 + 128;
        float a0=0,a1=0,a2=0,a3=0,a4=0,a5=0,a6=0,a7=0;
        #pragma unroll 8
        for (int i = i0; i < i1; i++) {
            float w = W1[i * HID + j];
            float4 hA = *(const float4*)&h0s[i * 8];
            float4 hB = *(const float4*)&h0s[i * 8 + 4];
            a0 += hA.x*w; a1 += hA.y*w; a2 += hA.z*w; a3 += hA.w*w;
            a4 += hB.x*w; a5 += hB.y*w; a6 += hB.z*w; a7 += hB.w*w;
        }
        *(float4*)&psum[(h*256+j)*8]   = make_float4(a0,a1,a2,a3);
        *(float4*)&psum[(h*256+j)*8+4] = make_float4(a4,a5,a6,a7);
    }
    __syncthreads();
    {
        int j = tid >> 1, q = (tid & 1) * 4;
        float4 pA = *(const float4*)&psum[j*8 + q];
        float4 pB = *(const float4*)&psum[(256+j)*8 + q];
        float bb = b1[j];
        *(float4*)&h1s[j*8+q] = make_float4(
            lrelu(pA.x+pB.x+bb), lrelu(pA.y+pB.y+bb),
            lrelu(pA.z+pB.z+bb), lrelu(pA.w+pB.w+bb));
    }
    __syncthreads();

    // ---- ctrl out: 256 -> 128, tanh, i split in 4 quarters ----
    {
        int j = tid & 127, qt = tid >> 7;
        int i0 = qt * 64, i1 = i0 + 64;
        float a0=0,a1=0,a2=0,a3=0,a4=0,a5=0,a6=0,a7=0;
        #pragma unroll 8
        for (int i = i0; i < i1; i++) {
            float w = Wout[i * COUT + j];
            float4 hA = *(const float4*)&h1s[i * 8];
            float4 hB = *(const float4*)&h1s[i * 8 + 4];
            a0 += hA.x*w; a1 += hA.y*w; a2 += hA.z*w; a3 += hA.w*w;
            a4 += hB.x*w; a5 += hB.y*w; a6 += hB.z*w; a7 += hB.w*w;
        }
        *(float4*)&psum[(qt*128+j)*8]   = make_float4(a0,a1,a2,a3);
        *(float4*)&psum[(qt*128+j)*8+4] = make_float4(a4,a5,a6,a7);
    }
    __syncthreads();
    if (tid < 256) {
        int j = tid >> 1, q = (tid & 1) * 4;
        float4 p0 = *(const float4*)&psum[(0*128+j)*8 + q];
        float4 p1 = *(const float4*)&psum[(1*128+j)*8 + q];
        float4 p2 = *(const float4*)&psum[(2*128+j)*8 + q];
        float4 p3 = *(const float4*)&psum[(3*128+j)*8 + q];
        float bb = bout[j];
        float v0 = tanhf_(p0.x+p1.x+p2.x+p3.x+bb);
        float v1 = tanhf_(p0.y+p1.y+p2.y+p3.y+bb);
        float v2 = tanhf_(p0.z+p1.z+p2.z+p3.z+bb);
        float v3 = tanhf_(p0.w+p1.w+p2.w+p3.w+bb);
        *(float4*)&cos_[j*8+q] = make_float4(v0,v1,v2,v3);
        int r0 = q;
        g_ctrl[(bbase + r0 + 0) * COUT + j] = v0;
        g_ctrl[(bbase + r0 + 1) * COUT + j] = v1;
        g_ctrl[(bbase + r0 + 2) * COUT + j] = v2;
        g_ctrl[(bbase + r0 + 3) * COUT + j] = v3;
    }
    __syncthreads();

    // ---- repr: 128 -> 268 ----
    for (int o = tid; o < REPR; o += 512) {
        float bb = rb[o];
        float a0=bb,a1=bb,a2=bb,a3=bb,a4=bb,a5=bb,a6=bb,a7=bb;
        #pragma unroll 8
        for (int i = 0; i < COUT; i++) {
            float w = rW[i * REPR + o];
            float4 hA = *(const float4*)&cos_[i * 8];
            float4 hB = *(const float4*)&cos_[i * 8 + 4];
            a0 += hA.x*w; a1 += hA.y*w; a2 += hA.z*w; a3 += hA.w*w;
            a4 += hB.x*w; a5 += hB.y*w; a6 += hB.z*w; a7 += hB.w*w;
        }
        rep[0][o]=a0; rep[1][o]=a1; rep[2][o]=a2; rep[3][o]=a3;
        rep[4][o]=a4; rep[5][o]=a5; rep[6][o]=a6; rep[7][o]=a7;
    }
    __syncthreads();

    for (int idx = tid; idx < ROWS * REPR; idx += 512) {
        int r = idx / REPR, o = idx % REPR;
        float v = rep[r][o], t;
        if (o < 2 * PARAM) {
            int oh = o % PARAM;
            if (oh < Mm)        t = tanhf_(v);
            else if (oh == Mm)  t = softplusf_(v);
            else if (oh == Mm+1)t = sigmoidf_(v);
            else if (oh < Mm+5) t = v;
            else                t = softplusf_(v)+1.f;
        } else if (o < 2 * PARAM + Mm) t = sigmoidf_(v);
        else                            t = tanhf_(v);
        rep[r][o] = t;
    }
    __syncthreads();

    const int lane = tid & 31, wid = tid >> 5;
    if (wid < ROWS) {
        int r = wid, b = bbase + r;
        #pragma unroll
        for (int h = 0; h < 2; h++) {
            float v0 = rep[r][h * PARAM + lane];
            float v1 = rep[r][h * PARAM + lane + 32];
            g_kt[b * 128 + h * 64 + lane]      = v0;
            g_kt[b * 128 + h * 64 + lane + 32] = v1;
            float ss = v0 * v0 + v1 * v1;
            #pragma unroll
            for (int o = 16; o; o >>= 1) ss += __shfl_xor_sync(0xffffffffu, ss, o);
            if (lane == 0) g_scal[b * 16 + h * 8 + 0] = sqrtf(ss);
        }
    }
    if (tid < 16) {
        int r = tid >> 1, h = tid & 1, b = bbase + r;
        const float* rp = &rep[r][h * PARAM];
        float* sp = &g_scal[b * 16 + h * 8];
        sp[1] = rp[Mm];
        sp[2] = rp[Mm + 1];
        sp[6] = rp[Mm + 5];
        float s0 = rp[Mm + 2], s1 = rp[Mm + 3], s2 = rp[Mm + 4];
        float mx = fmaxf(s0, fmaxf(s1, s2));
        float e0 = __expf(s0 - mx), e1 = __expf(s1 - mx), e2 = __expf(s2 - mx);
        float inv = 1.f / (e0 + e1 + e2);
        sp[3] = e0 * inv; sp[4] = e1 * inv; sp[5] = e2 * inv;
    }
    {
        int r = tid >> 6, m = tid & 63;
        g_ae[(bbase + r) * Mm + m] =
            rep[r][2 * PARAM + Mm + m] - rep[r][2 * PARAM + m];
    }
}

// ================= block reduction helper (512 threads) =====================
__device__ __forceinline__ void block_red2(float a, float b, float* oa, float* ob,
                                           float* scratch, bool is_max)
{
    #pragma unroll
    for (int o = 16; o; o >>= 1) {
        float ta = __shfl_xor_sync(0xffffffffu, a, o);
        float tb = __shfl_xor_sync(0xffffffffu, b, o);
        if (is_max) { a = fmaxf(a, ta); b = fmaxf(b, tb); }
        else        { a += ta;          b += tb; }
    }
    int w = threadIdx.x >> 5;
    __syncthreads();
    if ((threadIdx.x & 31) == 0) { scratch[w] = a; scratch[16 + w] = b; }
    __syncthreads();
    if (threadIdx.x < 16) {
        float va = scratch[threadIdx.x];
        float vb = scratch[16 + threadIdx.x];
        #pragma unroll
        for (int o = 8; o; o >>= 1) {
            float ta = __shfl_xor_sync(0xffffu, va, o);
            float tb = __shfl_xor_sync(0xffffu, vb, o);
            if (is_max) { va = fmaxf(va, ta); vb = fmaxf(vb, tb); }
            else        { va += ta;           vb += tb; }
        }
        if (threadIdx.x == 0) { scratch[0] = va; scratch[16] = vb; }
    }
    __syncthreads();
    *oa = scratch[0]; *ob = scratch[16];
}

// ===== Kernel 2: single-DRAM-read addressing via fp16 smem staging ==========
// R8 structure verbatim: 64 KB unpadded fp16 stash, red aliased onto dead
// wgr/wgw -> ~73 KB/CTA -> 3 CTAs/SM; pass 1 software-pipelined.
__global__ void __launch_bounds__(512, 3)
addr_kernel(const float* __restrict__ bank, const float* __restrict__ w_read,
            const float* __restrict__ w_write, float* __restrict__ out)
{
    extern __shared__ __half sbank[];     // Nn * SROW halves = 65536 B
    __shared__ float skt[128];
    __shared__ float sr[Nn], sw_[Nn];     // scores -> final weights
    __shared__ float wg2[2 * Nn];         // gate weights, then read partials
    __shared__ float aed[Mm];
    __shared__ float bc[32];

    float* wgr = wg2;
    float* wgw = wg2 + Nn;
    float* red = wg2;                     // aliased: wgr/wgw dead by pass 2

    const int b = blockIdx.x;
    const int tid = threadIdx.x;
    const int lane = tid & 31, wid = tid >> 5;

    if (tid < 128) skt[tid] = g_kt[b * 128 + tid];
    if (tid < 64)  aed[tid] = g_ae[b * 64 + tid];
    __syncthreads();

    const float4* gb4 = (const float4*)(bank + (size_t)b * Nn * Mm);
    const float* sp = &g_scal[b * 16];
    const int g8 = tid >> 3;           // row-group 0..63
    const int mo = (tid & 7) * 8;      // m offset (floats/halves)

    // ---- pass 1: stream bank once (pipelined) -> scores + fp16 stash ----
    {
        const float4 ktr0 = *(const float4*)&skt[mo];
        const float4 ktr1 = *(const float4*)&skt[mo + 4];
        const float4 ktw0 = *(const float4*)&skt[64 + mo];
        const float4 ktw1 = *(const float4*)&skt[64 + mo + 4];
        const float knorm_r = sp[0], beta_r = sp[1];
        const float knorm_w = sp[8], beta_w = sp[9];

        const float4* row0 = gb4 + g8 * 16 + (mo >> 2);
        float4 x0 = __ldcs(&row0[0]);
        float4 x1 = __ldcs(&row0[1]);
        #pragma unroll
        for (int it = 0; it < 8; it++) {
            float4 y0, y1;
            if (it < 7) {
                const float4* rn = gb4 + ((it + 1) * 64 + g8) * 16 + (mo >> 2);
                y0 = __ldcs(&rn[0]);
                y1 = __ldcs(&rn[1]);
            }
            int n = it * 64 + g8;
            union { __half2 h[4]; uint4 u; } cv;
            cv.h[0] = __floats2half2_rn(x0.x, x0.y);
            cv.h[1] = __floats2half2_rn(x0.z, x0.w);
            cv.h[2] = __floats2half2_rn(x1.x, x1.y);
            cv.h[3] = __floats2half2_rn(x1.z, x1.w);
            *(uint4*)&sbank[n * SROW + mo] = cv.u;

            float dr = x0.x*ktr0.x + x0.y*ktr0.y + x0.z*ktr0.z + x0.w*ktr0.w
                     + x1.x*ktr1.x + x1.y*ktr1.y + x1.z*ktr1.z + x1.w*ktr1.w;
            float dw = x0.x*ktw0.x + x0.y*ktw0.y + x0.z*ktw0.z + x0.w*ktw0.w
                     + x1.x*ktw1.x + x1.y*ktw1.y + x1.z*ktw1.z + x1.w*ktw1.w;
            float ss = x0.x*x0.x + x0.y*x0.y + x0.z*x0.z + x0.w*x0.w
                     + x1.x*x1.x + x1.y*x1.y + x1.z*x1.z + x1.w*x1.w;
            #pragma unroll
            for (int o = 4; o; o >>= 1) {
                dr += __shfl_xor_sync(0xffffffffu, dr, o);
                dw += __shfl_xor_sync(0xffffffffu, dw, o);
                ss += __shfl_xor_sync(0xffffffffu, ss, o);
            }
            if ((tid & 7) == 0) {
                float nb = sqrtf(ss);
                sr[n]  = beta_r * dr / fmaxf(nb * knorm_r, 1e-8f);
                sw_[n] = beta_w * dw / fmaxf(nb * knorm_w, 1e-8f);
            }
            x0 = y0; x1 = y1;
        }
    }
    __syncthreads();

    // ---- softmax over N, gate interpolation ----
    {
        const float gg_r = sp[2], gg_w = sp[10];
        float vr = sr[tid], vw = sw_[tid];
        float mr, mw;  block_red2(vr, vw, &mr, &mw, bc, true);
        float er = __expf(vr - mr), ew = __expf(vw - mw);
        float srr, sww;  block_red2(er, ew, &srr, &sww, bc, false);
        float wgrv = gg_r * (er / srr) + (1.f - gg_r) * w_read [(size_t)b * Nn + tid];
        float wgwv = gg_w * (ew / sww) + (1.f - gg_w) * w_write[(size_t)b * Nn + tid];
        wgr[tid] = wgrv; wgw[tid] = wgwv;
    }
    __syncthreads();

    // ---- circular shift (-1,0,1) + sharpen + renormalize ----
    {
        const float sm0_r = sp[3], sm1_r = sp[4], sm2_r = sp[5], gam_r = sp[6];
        const float sm0_w = sp[11], sm1_w = sp[12], sm2_w = sp[13], gam_w = sp[14];
        int nm1 = (tid - 1) & (Nn - 1), np1 = (tid + 1) & (Nn - 1);
        float wsr = wgr[nm1] * sm0_r + wgr[tid] * sm1_r + wgr[np1] * sm2_r;
        float wsw = wgw[nm1] * sm0_w + wgw[tid] * sm1_w + wgw[np1] * sm2_w;
        float pr = __powf(wsr, gam_r), pw = __powf(wsw, gam_w);
        float spr, spw; block_red2(pr, pw, &spr, &spw, bc, false);
        sr[tid]  = pr / spr;   // final read weights
        sw_[tid] = pw / spw;   // final write weights
    }
    __syncthreads();

    // ---- pass 2: smem only -> read vector + new_bank write ----
    {
        const float4 ae0 = *(const float4*)&aed[mo];
        const float4 ae1 = *(const float4*)&aed[mo + 4];
        float racc[8] = {0,0,0,0,0,0,0,0};
        float4* ob4 = (float4*)(out + (size_t)Bsz * SEQW + (size_t)b * Nn * Mm);
        #pragma unroll
        for (int it = 0; it < 8; it++) {
            int n = it * 64 + g8;
            union { uint4 u; __half2 h[4]; } cv;
            cv.u = *(const uint4*)&sbank[n * SROW + mo];
            float2 f0 = __half22float2(cv.h[0]);
            float2 f1 = __half22float2(cv.h[1]);
            float2 f2 = __half22float2(cv.h[2]);
            float2 f3 = __half22float2(cv.h[3]);
            float wwv = sw_[n], wrv = sr[n];
            float4 o0 = make_float4(f0.x + wwv*ae0.x, f0.y + wwv*ae0.y,
                                    f1.x + wwv*ae0.z, f1.y + wwv*ae0.w);
            float4 o1 = make_float4(f2.x + wwv*ae1.x, f2.y + wwv*ae1.y,
                                    f3.x + wwv*ae1.z, f3.y + wwv*ae1.w);
            float4* op = ob4 + n * 16 + (mo >> 2);
            __stcs(&op[0], o0);
            __stcs(&op[1], o1);
            racc[0] += wrv*f0.x; racc[1] += wrv*f0.y;
            racc[2] += wrv*f1.x; racc[3] += wrv*f1.y;
            racc[4] += wrv*f2.x; racc[5] += wrv*f2.y;
            racc[6] += wrv*f3.x; racc[7] += wrv*f3.y;
        }
        // reduce over the 4 row-groups within each warp (lanes xor 8, 16)
        #pragma unroll
        for (int k = 0; k < 8; k++) {
            racc[k] += __shfl_xor_sync(0xffffffffu, racc[k], 8);
            racc[k] += __shfl_xor_sync(0xffffffffu, racc[k], 16);
        }
        __syncthreads();   // wgr/wgw dead; red aliases them
        if (lane < 8) {
            #pragma unroll
            for (int k = 0; k < 8; k++)
                red[wid * 64 + lane * 8 + k] = racc[k];
        }
    }
    __syncthreads();
    if (tid < 64) {
        float s = 0.f;
        #pragma unroll
        for (int w = 0; w < 16; w++) s += red[w * 64 + tid];
        g_read[b * 64 + tid] = s;
    }
}

// ================= Kernel 3: output projection ==============================
__global__ void __launch_bounds__(256)
out_kernel(const float* __restrict__ oW, const float* __restrict__ ob,
           float* __restrict__ out)
{
    __shared__ float sw[(COUT + Mm) * SEQW];  // 192*8
    __shared__ float sb[SEQW];
    for (int i = threadIdx.x; i < (COUT + Mm) * SEQW; i += 256) sw[i] = oW[i];
    if (threadIdx.x < SEQW) sb[threadIdx.x] = ob[threadIdx.x];
    __syncthreads();

    int gid = blockIdx.x * 256 + threadIdx.x;   // Bsz*SEQW total
    int b = gid >> 3, o = gid & 7;
    float acc = sb[o];
    const float* cp = g_ctrl + b * COUT;
    const float* rp = g_read + b * Mm;
    #pragma unroll 4
    for (int i = 0; i < COUT; i++) acc += cp[i] * sw[i * SEQW + o];
    #pragma unroll 4
    for (int i = 0; i < Mm; i++)  acc += rp[i] * sw[(COUT + i) * SEQW + o];
    out[b * SEQW + o] = 1.f / (1.f + __expf(-acc));
}

// ================= launch ====================================================
extern "C" void kernel_launch(void* const* d_in, const int* in_sizes, int n_in,
                              void* d_out, int out_size)
{
    const float* x         = (const float*)d_in[0];
    const float* prev_read = (const float*)d_in[1];
    const float* bank      = (const float*)d_in[2];
    const float* w_read    = (const float*)d_in[3];
    const float* w_write   = (const float*)d_in[4];
    const float* W0        = (const float*)d_in[5];
    const float* b0        = (const float*)d_in[6];
    const float* W1        = (const float*)d_in[7];
    const float* b1        = (const float*)d_in[8];
    const float* Wout      = (const float*)d_in[9];
    const float* bout      = (const float*)d_in[10];
    const float* rW        = (const float*)d_in[11];
    const float* rb        = (const float*)d_in[12];
    const float* oW        = (const float*)d_in[13];
    const float* ob        = (const float*)d_in[14];
    float* out = (float*)d_out;

    const int HBANK = Nn * SROW * (int)sizeof(__half);   // 65536 B dynamic smem
    cudaFuncSetAttribute(addr_kernel, cudaFuncAttributeMaxDynamicSharedMemorySize, HBANK);

    ctrl_kernel<<<Bsz / ROWS, 512>>>(x, prev_read, W0, b0, W1, b1, Wout, bout, rW, rb);
    addr_kernel<<<Bsz, 512, HBANK>>>(bank, w_read, w_write, out);
    out_kernel<<<Bsz * SEQW / 256, 256>>>(oW, ob, out);
}

// round 15
// speedup vs baseline: 1.1933x; 1.0137x over previous
#include <cuda_runtime.h>
#include <cuda_fp16.h>
#include <math.h>

#define Bsz 4096
#define Nn 512
#define Mm 64
#define SEQW 8
#define HID 256
#define COUT 128
#define IN_SIZE 73        // SEQW+1+Mm
#define PARAM 70          // M + 1 + 1 + 3 + 1
#define REPR 268          // 2*PARAM + 2*M
#define ROWS 8
#define SROW 64           // smem row stride in halves (128 B rows, no pad)

// ---------------- scratch (no cudaMalloc allowed) ----------------
__device__ float g_ctrl[Bsz * COUT];     // controller output
__device__ float g_kt[Bsz * 2 * Mm];     // tanh'd keys [b][head][m]
__device__ float g_scal[Bsz * 16];       // per (b,head): knorm,beta,gg,sm0..2,gamma
__device__ float g_ae[Bsz * Mm];         // a - e
__device__ float g_read[Bsz * Mm];       // read vector

__device__ __forceinline__ float lrelu(float x)    { return x > 0.f ? x : 0.01f * x; }
__device__ __forceinline__ float sigmoidf_(float x){ return 1.f / (1.f + __expf(-x)); }
__device__ __forceinline__ float softplusf_(float x){ return x > 20.f ? x : log1pf(__expf(x)); }
__device__ __forceinline__ float tanhf_(float x)   {
    float e = __expf(2.f * x);
    float t = 1.f - 2.f / (e + 1.f);
    return (x > 9.f) ? 1.f : (x < -9.f ? -1.f : t);
}

// ========= Kernel 1: controller + repr (8 rows, 512 thr, split-K) ===========
// minBlocksPerMultiprocessor=4 caps regs at 32 -> 4 CTAs/SM, single wave.
__global__ void __launch_bounds__(512, 4)
ctrl_kernel(const float* __restrict__ x, const float* __restrict__ prev_read,
            const float* __restrict__ W0, const float* __restrict__ b0,
            const float* __restrict__ W1, const float* __restrict__ b1,
            const float* __restrict__ Wout, const float* __restrict__ bout,
            const float* __restrict__ rW, const float* __restrict__ rb)
{
    __shared__ float cin[IN_SIZE * ROWS];   // [i][r]
    __shared__ float h0s[HID * ROWS];       // [i][r]
    __shared__ float h1s[HID * ROWS];       // [i][r]
    __shared__ float cos_[COUT * ROWS];     // [i][r]
    __shared__ float rep[ROWS][REPR];
    __shared__ float psum[4096];            // split-K partials

    const int tid = threadIdx.x;
    const int bbase = blockIdx.x * ROWS;

    for (int idx = tid; idx < IN_SIZE * ROWS; idx += 512) {
        int i = idx >> 3, r = idx & 7;
        int b = bbase + r;
        cin[idx] = (i < SEQW + 1) ? x[b * (SEQW + 1) + i]
                                  : prev_read[b * Mm + (i - (SEQW + 1))];
    }
    __syncthreads();

    // ---- layer 0: 73 -> 256, i split in 2 halves ----
    {
        int j = tid & 255, h = tid >> 8;
        int i0 = h ? 37 : 0, i1 = h ? 73 : 37;
        float a0=0,a1=0,a2=0,a3=0,a4=0,a5=0,a6=0,a7=0;
        #pragma unroll 4
        for (int i = i0; i < i1; i++) {
            float w = W0[i * HID + j];
            float4 hA = *(const float4*)&cin[i * 8];
            float4 hB = *(const float4*)&cin[i * 8 + 4];
            a0 += hA.x*w; a1 += hA.y*w; a2 += hA.z*w; a3 += hA.w*w;
            a4 += hB.x*w; a5 += hB.y*w; a6 += hB.z*w; a7 += hB.w*w;
        }
        *(float4*)&psum[(h*256+j)*8]   = make_float4(a0,a1,a2,a3);
        *(float4*)&psum[(h*256+j)*8+4] = make_float4(a4,a5,a6,a7);
    }
    __syncthreads();
    {
        int j = tid >> 1, q = (tid & 1) * 4;
        float4 pA = *(const float4*)&psum[j*8 + q];
        float4 pB = *(const float4*)&psum[(256+j)*8 + q];
        float bb = b0[j];
        *(float4*)&h0s[j*8+q] = make_float4(
            lrelu(pA.x+pB.x+bb), lrelu(pA.y+pB.y+bb),
            lrelu(pA.z+pB.z+bb), lrelu(pA.w+pB.w+bb));
    }
    __syncthreads();

    // ---- layer 1: 256 -> 256, i split in 2 halves ----
    {
        int j = tid & 255, h = tid >> 8;
        int i0 = h * 128, i1 = i0 + 128;
        float a0=0,a1=0,a2=0,a3=0,a4=0,a5=0,a6=0,a7=0;
        #pragma unroll 8
        for (int i = i0; i < i1; i++) {
            float w = W1[i * HID + j];
            float4 hA = *(const float4*)&h0s[i * 8];
            float4 hB = *(const float4*)&h0s[i * 8 + 4];
            a0 += hA.x*w; a1 += hA.y*w; a2 += hA.z*w; a3 += hA.w*w;
            a4 += hB.x*w; a5 += hB.y*w; a6 += hB.z*w; a7 += hB.w*w;
        }
        *(float4*)&psum[(h*256+j)*8]   = make_float4(a0,a1,a2,a3);
        *(float4*)&psum[(h*256+j)*8+4] = make_float4(a4,a5,a6,a7);
    }
    __syncthreads();
    {
        int j = tid >> 1, q = (tid & 1) * 4;
        float4 pA = *(const float4*)&psum[j*8 + q];
        float4 pB = *(const float4*)&psum[(256+j)*8 + q];
        float bb = b1[j];
        *(float4*)&h1s[j*8+q] = make_float4(
            lrelu(pA.x+pB.x+bb), lrelu(pA.y+pB.y+bb),
            lrelu(pA.z+pB.z+bb), lrelu(pA.w+pB.w+bb));
    }
    __syncthreads();

    // ---- ctrl out: 256 -> 128, tanh, i split in 4 quarters ----
    {
        int j = tid & 127, qt = tid >> 7;
        int i0 = qt * 64, i1 = i0 + 64;
        float a0=0,a1=0,a2=0,a3=0,a4=0,a5=0,a6=0,a7=0;
        #pragma unroll 8
        for (int i = i0; i < i1; i++) {
            float w = Wout[i * COUT + j];
            float4 hA = *(const float4*)&h1s[i * 8];
            float4 hB = *(const float4*)&h1s[i * 8 + 4];
            a0 += hA.x*w; a1 += hA.y*w; a2 += hA.z*w; a3 += hA.w*w;
            a4 += hB.x*w; a5 += hB.y*w; a6 += hB.z*w; a7 += hB.w*w;
        }
        *(float4*)&psum[(qt*128+j)*8]   = make_float4(a0,a1,a2,a3);
        *(float4*)&psum[(qt*128+j)*8+4] = make_float4(a4,a5,a6,a7);
    }
    __syncthreads();
    if (tid < 256) {
        int j = tid >> 1, q = (tid & 1) * 4;
        float4 p0 = *(const float4*)&psum[(0*128+j)*8 + q];
        float4 p1 = *(const float4*)&psum[(1*128+j)*8 + q];
        float4 p2 = *(const float4*)&psum[(2*128+j)*8 + q];
        float4 p3 = *(const float4*)&psum[(3*128+j)*8 + q];
        float bb = bout[j];
        float v0 = tanhf_(p0.x+p1.x+p2.x+p3.x+bb);
        float v1 = tanhf_(p0.y+p1.y+p2.y+p3.y+bb);
        float v2 = tanhf_(p0.z+p1.z+p2.z+p3.z+bb);
        float v3 = tanhf_(p0.w+p1.w+p2.w+p3.w+bb);
        *(float4*)&cos_[j*8+q] = make_float4(v0,v1,v2,v3);
        int r0 = q;
        g_ctrl[(bbase + r0 + 0) * COUT + j] = v0;
        g_ctrl[(bbase + r0 + 1) * COUT + j] = v1;
        g_ctrl[(bbase + r0 + 2) * COUT + j] = v2;
        g_ctrl[(bbase + r0 + 3) * COUT + j] = v3;
    }
    __syncthreads();

    // ---- repr: 128 -> 268 ----
    for (int o = tid; o < REPR; o += 512) {
        float bb = rb[o];
        float a0=bb,a1=bb,a2=bb,a3=bb,a4=bb,a5=bb,a6=bb,a7=bb;
        #pragma unroll 8
        for (int i = 0; i < COUT; i++) {
            float w = rW[i * REPR + o];
            float4 hA = *(const float4*)&cos_[i * 8];
            float4 hB = *(const float4*)&cos_[i * 8 + 4];
            a0 += hA.x*w; a1 += hA.y*w; a2 += hA.z*w; a3 += hA.w*w;
            a4 += hB.x*w; a5 += hB.y*w; a6 += hB.z*w; a7 += hB.w*w;
        }
        rep[0][o]=a0; rep[1][o]=a1; rep[2][o]=a2; rep[3][o]=a3;
        rep[4][o]=a4; rep[5][o]=a5; rep[6][o]=a6; rep[7][o]=a7;
    }
    __syncthreads();

    for (int idx = tid; idx < ROWS * REPR; idx += 512) {
        int r = idx / REPR, o = idx % REPR;
        float v = rep[r][o], t;
        if (o < 2 * PARAM) {
            int oh = o % PARAM;
            if (oh < Mm)        t = tanhf_(v);
            else if (oh == Mm)  t = softplusf_(v);
            else if (oh == Mm+1)t = sigmoidf_(v);
            else if (oh < Mm+5) t = v;
            else                t = softplusf_(v)+1.f;
        } else if (o < 2 * PARAM + Mm) t = sigmoidf_(v);
        else                            t = tanhf_(v);
        rep[r][o] = t;
    }
    __syncthreads();

    const int lane = tid & 31, wid = tid >> 5;
    if (wid < ROWS) {
        int r = wid, b = bbase + r;
        #pragma unroll
        for (int h = 0; h < 2; h++) {
            float v0 = rep[r][h * PARAM + lane];
            float v1 = rep[r][h * PARAM + lane + 32];
            g_kt[b * 128 + h * 64 + lane]      = v0;
            g_kt[b * 128 + h * 64 + lane + 32] = v1;
            float ss = v0 * v0 + v1 * v1;
            #pragma unroll
            for (int o = 16; o; o >>= 1) ss += __shfl_xor_sync(0xffffffffu, ss, o);
            if (lane == 0) g_scal[b * 16 + h * 8 + 0] = sqrtf(ss);
        }
    }
    if (tid < 16) {
        int r = tid >> 1, h = tid & 1, b = bbase + r;
        const float* rp = &rep[r][h * PARAM];
        float* sp = &g_scal[b * 16 + h * 8];
        sp[1] = rp[Mm];
        sp[2] = rp[Mm + 1];
        sp[6] = rp[Mm + 5];
        float s0 = rp[Mm + 2], s1 = rp[Mm + 3], s2 = rp[Mm + 4];
        float mx = fmaxf(s0, fmaxf(s1, s2));
        float e0 = __expf(s0 - mx), e1 = __expf(s1 - mx), e2 = __expf(s2 - mx);
        float inv = 1.f / (e0 + e1 + e2);
        sp[3] = e0 * inv; sp[4] = e1 * inv; sp[5] = e2 * inv;
    }
    {
        int r = tid >> 6, m = tid & 63;
        g_ae[(bbase + r) * Mm + m] =
            rep[r][2 * PARAM + Mm + m] - rep[r][2 * PARAM + m];
    }
}

// ================= block reduction helper (512 threads) =====================
__device__ __forceinline__ void block_red2(float a, float b, float* oa, float* ob,
                                           float* scratch, bool is_max)
{
    #pragma unroll
    for (int o = 16; o; o >>= 1) {
        float ta = __shfl_xor_sync(0xffffffffu, a, o);
        float tb = __shfl_xor_sync(0xffffffffu, b, o);
        if (is_max) { a = fmaxf(a, ta); b = fmaxf(b, tb); }
        else        { a += ta;          b += tb; }
    }
    int w = threadIdx.x >> 5;
    __syncthreads();
    if ((threadIdx.x & 31) == 0) { scratch[w] = a; scratch[16 + w] = b; }
    __syncthreads();
    if (threadIdx.x < 16) {
        float va = scratch[threadIdx.x];
        float vb = scratch[16 + threadIdx.x];
        #pragma unroll
        for (int o = 8; o; o >>= 1) {
            float ta = __shfl_xor_sync(0xffffu, va, o);
            float tb = __shfl_xor_sync(0xffffu, vb, o);
            if (is_max) { va = fmaxf(va, ta); vb = fmaxf(vb, tb); }
            else        { va += ta;           vb += tb; }
        }
        if (threadIdx.x == 0) { scratch[0] = va; scratch[16] = vb; }
    }
    __syncthreads();
    *oa = scratch[0]; *ob = scratch[16];
}

// ===== Kernel 2: single-DRAM-read addressing via fp16 smem staging ==========
// R8 structure; softmax without max-subtraction (scores are fp32-safe
// bounded), saving one full block reduction per element.
__global__ void __launch_bounds__(512, 3)
addr_kernel(const float* __restrict__ bank, const float* __restrict__ w_read,
            const float* __restrict__ w_write, float* __restrict__ out)
{
    extern __shared__ __half sbank[];     // Nn * SROW halves = 65536 B
    __shared__ float skt[128];
    __shared__ float sr[Nn], sw_[Nn];     // scores -> final weights
    __shared__ float wg2[2 * Nn];         // gate weights, then read partials
    __shared__ float aed[Mm];
    __shared__ float bc[32];

    float* wgr = wg2;
    float* wgw = wg2 + Nn;
    float* red = wg2;                     // aliased: wgr/wgw dead by pass 2

    const int b = blockIdx.x;
    const int tid = threadIdx.x;
    const int lane = tid & 31, wid = tid >> 5;

    if (tid < 128) skt[tid] = g_kt[b * 128 + tid];
    if (tid < 64)  aed[tid] = g_ae[b * 64 + tid];
    __syncthreads();

    const float4* gb4 = (const float4*)(bank + (size_t)b * Nn * Mm);
    const float* sp = &g_scal[b * 16];
    const int g8 = tid >> 3;           // row-group 0..63
    const int mo = (tid & 7) * 8;      // m offset (floats/halves)

    // ---- pass 1: stream bank once (pipelined) -> scores + fp16 stash ----
    {
        const float4 ktr0 = *(const float4*)&skt[mo];
        const float4 ktr1 = *(const float4*)&skt[mo + 4];
        const float4 ktw0 = *(const float4*)&skt[64 + mo];
        const float4 ktw1 = *(const float4*)&skt[64 + mo + 4];
        const float knorm_r = sp[0], beta_r = sp[1];
        const float knorm_w = sp[8], beta_w = sp[9];

        const float4* row0 = gb4 + g8 * 16 + (mo >> 2);
        float4 x0 = __ldcs(&row0[0]);
        float4 x1 = __ldcs(&row0[1]);
        #pragma unroll
        for (int it = 0; it < 8; it++) {
            float4 y0, y1;
            if (it < 7) {
                const float4* rn = gb4 + ((it + 1) * 64 + g8) * 16 + (mo >> 2);
                y0 = __ldcs(&rn[0]);
                y1 = __ldcs(&rn[1]);
            }
            int n = it * 64 + g8;
            union { __half2 h[4]; uint4 u; } cv;
            cv.h[0] = __floats2half2_rn(x0.x, x0.y);
            cv.h[1] = __floats2half2_rn(x0.z, x0.w);
            cv.h[2] = __floats2half2_rn(x1.x, x1.y);
            cv.h[3] = __floats2half2_rn(x1.z, x1.w);
            *(uint4*)&sbank[n * SROW + mo] = cv.u;

            float dr = x0.x*ktr0.x + x0.y*ktr0.y + x0.z*ktr0.z + x0.w*ktr0.w
                     + x1.x*ktr1.x + x1.y*ktr1.y + x1.z*ktr1.z + x1.w*ktr1.w;
            float dw = x0.x*ktw0.x + x0.y*ktw0.y + x0.z*ktw0.z + x0.w*ktw0.w
                     + x1.x*ktw1.x + x1.y*ktw1.y + x1.z*ktw1.z + x1.w*ktw1.w;
            float ss = x0.x*x0.x + x0.y*x0.y + x0.z*x0.z + x0.w*x0.w
                     + x1.x*x1.x + x1.y*x1.y + x1.z*x1.z + x1.w*x1.w;
            #pragma unroll
            for (int o = 4; o; o >>= 1) {
                dr += __shfl_xor_sync(0xffffffffu, dr, o);
                dw += __shfl_xor_sync(0xffffffffu, dw, o);
                ss += __shfl_xor_sync(0xffffffffu, ss, o);
            }
            if ((tid & 7) == 0) {
                float nb = sqrtf(ss);
                sr[n]  = beta_r * dr * __frcp_rn(fmaxf(nb * knorm_r, 1e-8f));
                sw_[n] = beta_w * dw * __frcp_rn(fmaxf(nb * knorm_w, 1e-8f));
            }
            x0 = y0; x1 = y1;
        }
    }
    __syncthreads();

    // ---- softmax over N (no max subtraction: |score| <= beta, fp32-safe) ----
    {
        const float gg_r = sp[2], gg_w = sp[10];
        float er = __expf(sr[tid]), ew = __expf(sw_[tid]);
        float srr, sww;  block_red2(er, ew, &srr, &sww, bc, false);
        float isr = __frcp_rn(srr), isw = __frcp_rn(sww);
        float wgrv = gg_r * (er * isr) + (1.f - gg_r) * w_read [(size_t)b * Nn + tid];
        float wgwv = gg_w * (ew * isw) + (1.f - gg_w) * w_write[(size_t)b * Nn + tid];
        wgr[tid] = wgrv; wgw[tid] = wgwv;
    }
    __syncthreads();

    // ---- circular shift (-1,0,1) + sharpen + renormalize ----
    {
        const float sm0_r = sp[3], sm1_r = sp[4], sm2_r = sp[5], gam_r = sp[6];
        const float sm0_w = sp[11], sm1_w = sp[12], sm2_w = sp[13], gam_w = sp[14];
        int nm1 = (tid - 1) & (Nn - 1), np1 = (tid + 1) & (Nn - 1);
        float wsr = wgr[nm1] * sm0_r + wgr[tid] * sm1_r + wgr[np1] * sm2_r;
        float wsw = wgw[nm1] * sm0_w + wgw[tid] * sm1_w + wgw[np1] * sm2_w;
        float pr = __powf(wsr, gam_r), pw = __powf(wsw, gam_w);
        float spr, spw; block_red2(pr, pw, &spr, &spw, bc, false);
        sr[tid]  = pr * __frcp_rn(spr);   // final read weights
        sw_[tid] = pw * __frcp_rn(spw);   // final write weights
    }
    __syncthreads();

    // ---- pass 2: smem only -> read vector + new_bank write ----
    {
        const float4 ae0 = *(const float4*)&aed[mo];
        const float4 ae1 = *(const float4*)&aed[mo + 4];
        float racc[8] = {0,0,0,0,0,0,0,0};
        float4* ob4 = (float4*)(out + (size_t)Bsz * SEQW + (size_t)b * Nn * Mm);
        #pragma unroll
        for (int it = 0; it < 8; it++) {
            int n = it * 64 + g8;
            union { uint4 u; __half2 h[4]; } cv;
            cv.u = *(const uint4*)&sbank[n * SROW + mo];
            float2 f0 = __half22float2(cv.h[0]);
            float2 f1 = __half22float2(cv.h[1]);
            float2 f2 = __half22float2(cv.h[2]);
            float2 f3 = __half22float2(cv.h[3]);
            float wwv = sw_[n], wrv = sr[n];
            float4 o0 = make_float4(f0.x + wwv*ae0.x, f0.y + wwv*ae0.y,
                                    f1.x + wwv*ae0.z, f1.y + wwv*ae0.w);
            float4 o1 = make_float4(f2.x + wwv*ae1.x, f2.y + wwv*ae1.y,
                                    f3.x + wwv*ae1.z, f3.y + wwv*ae1.w);
            float4* op = ob4 + n * 16 + (mo >> 2);
            __stcs(&op[0], o0);
            __stcs(&op[1], o1);
            racc[0] += wrv*f0.x; racc[1] += wrv*f0.y;
            racc[2] += wrv*f1.x; racc[3] += wrv*f1.y;
            racc[4] += wrv*f2.x; racc[5] += wrv*f2.y;
            racc[6] += wrv*f3.x; racc[7] += wrv*f3.y;
        }
        // reduce over the 4 row-groups within each warp (lanes xor 8, 16)
        #pragma unroll
        for (int k = 0; k < 8; k++) {
            racc[k] += __shfl_xor_sync(0xffffffffu, racc[k], 8);
            racc[k] += __shfl_xor_sync(0xffffffffu, racc[k], 16);
        }
        __syncthreads();   // wgr/wgw dead; red aliases them
        if (lane < 8) {
            #pragma unroll
            for (int k = 0; k < 8; k++)
                red[wid * 64 + lane * 8 + k] = racc[k];
        }
    }
    __syncthreads();
    if (tid < 64) {
        float s = 0.f;
        #pragma unroll
        for (int w = 0; w < 16; w++) s += red[w * 64 + tid];
        g_read[b * 64 + tid] = s;
    }
}

// ================= Kernel 3: output projection ==============================
__global__ void __launch_bounds__(256)
out_kernel(const float* __restrict__ oW, const float* __restrict__ ob,
           float* __restrict__ out)
{
    __shared__ float sw[(COUT + Mm) * SEQW];  // 192*8
    __shared__ float sb[SEQW];
    for (int i = threadIdx.x; i < (COUT + Mm) * SEQW; i += 256) sw[i] = oW[i];
    if (threadIdx.x < SEQW) sb[threadIdx.x] = ob[threadIdx.x];
    __syncthreads();

    int gid = blockIdx.x * 256 + threadIdx.x;   // Bsz*SEQW total
    int b = gid >> 3, o = gid & 7;
    float acc = sb[o];
    const float* cp = g_ctrl + b * COUT;
    const float* rp = g_read + b * Mm;
    #pragma unroll 4
    for (int i = 0; i < COUT; i++) acc += cp[i] * sw[i * SEQW + o];
    #pragma unroll 4
    for (int i = 0; i < Mm; i++)  acc += rp[i] * sw[(COUT + i) * SEQW + o];
    out[b * SEQW + o] = 1.f / (1.f + __expf(-acc));
}

// ================= launch ====================================================
extern "C" void kernel_launch(void* const* d_in, const int* in_sizes, int n_in,
                              void* d_out, int out_size)
{
    const float* x         = (const float*)d_in[0];
    const float* prev_read = (const float*)d_in[1];
    const float* bank      = (const float*)d_in[2];
    const float* w_read    = (const float*)d_in[3];
    const float* w_write   = (const float*)d_in[4];
    const float* W0        = (const float*)d_in[5];
    const float* b0        = (const float*)d_in[6];
    const float* W1        = (const float*)d_in[7];
    const float* b1        = (const float*)d_in[8];
    const float* Wout      = (const float*)d_in[9];
    const float* bout      = (const float*)d_in[10];
    const float* rW        = (const float*)d_in[11];
    const float* rb        = (const float*)d_in[12];
    const float* oW        = (const float*)d_in[13];
    const float* ob        = (const float*)d_in[14];
    float* out = (float*)d_out;

    const int HBANK = Nn * SROW * (int)sizeof(__half);   // 65536 B dynamic smem
    cudaFuncSetAttribute(addr_kernel, cudaFuncAttributeMaxDynamicSharedMemorySize, HBANK);

    ctrl_kernel<<<Bsz / ROWS, 512>>>(x, prev_read, W0, b0, W1, b1, Wout, bout, rW, rb);
    addr_kernel<<<Bsz, 512, HBANK>>>(bank, w_read, w_write, out);
    out_kernel<<<Bsz * SEQW / 256, 256>>>(oW, ob, out);
}